// round 11
// baseline (speedup 1.0000x reference)
#include <cuda_runtime.h>
#include <cuda_bf16.h>
#include <mma.h>
#include <math.h>
#include <stdint.h>

using namespace nvcuda;

#define NVOC 50257
#define NIN  1024
#define NH   1024
#define H2   2048
#define G4   8192
#define BB   64
#define TT   1024

// ---------------- scratch ----------------
__device__ float g_wa[BB*NH];
__device__ float g_score[TT*BB];
__device__ float g_ctx[BB*NH];
__device__ float g_emb[BB*NIN];
__device__ float g_gp[3][BB*G4];
__device__ __nv_bfloat16 g_Uh[NH*NH];   // attUa in bf16, [k][n] layout

__device__ __forceinline__ float tanh_approx(float x) {
    float y; asm("tanh.approx.f32 %0, %1;" : "=f"(y) : "f"(x)); return y;
}
__device__ __forceinline__ float sigmoid_acc(float x) {
    return 1.0f / (1.0f + expf(-x));
}

// ---------------- 1: zero score + gather emb + convert attUa (merged) -------
__global__ void k_pre(const int* __restrict__ inputs,
                      const float* __restrict__ enc_w,
                      const float* __restrict__ attUa) {
    int idx = blockIdx.x * blockDim.x + threadIdx.x;   // 0..327679
    if (idx < 65536) {
        g_score[idx] = 0.0f;
        int b = idx >> 10, c = idx & 1023;
        g_emb[idx] = enc_w[(size_t)inputs[b] * NIN + c];
    } else {
        int q = idx - 65536;                           // float4 index, 262144
        float4 v = *(const float4*)(attUa + (size_t)q * 4);
        __nv_bfloat162 h0 = __float22bfloat162_rn(make_float2(v.x, v.y));
        __nv_bfloat162 h1 = __float22bfloat162_rn(make_float2(v.z, v.w));
        uint2 u; u.x = *(unsigned*)&h0; u.y = *(unsigned*)&h1;
        *(uint2*)&g_Uh[(size_t)q * 4] = u;
    }
}

// ============================================================
// 2: wa = h_prev @ attWa   (64 x 1024, K=1024) — tf32 wmma
// ============================================================
__global__ __launch_bounds__(256) void k_wa(const float* __restrict__ h_prev,
                                            const float* __restrict__ attWa) {
    __shared__ float sm[8448];
    float* As = sm;
    float* Bs = sm + 2 * 64 * 20;
    float* Cs = sm;

    const int n0  = blockIdx.x * 128;
    const int tid = threadIdx.x;
    const int wid = tid >> 5;
    const int wm  = wid >> 2, wn = wid & 3;

    wmma::fragment<wmma::accumulator, 16, 16, 8, float> acc[2][2];
#pragma unroll
    for (int i = 0; i < 2; i++)
#pragma unroll
        for (int j = 0; j < 2; j++) wmma::fill_fragment(acc[i][j], 0.0f);

    const int am = tid >> 2, aq = tid & 3;
    const int br = tid >> 4, bseg = tid & 15;

    float4 ra, rb0, rb1;
    auto ldA = [&](int k0) { ra = *(const float4*)(h_prev + am * NH + k0 + aq * 4); };
    auto ldB = [&](int k0) {
        const float* p = attWa + (size_t)(k0 + br) * NH + n0 + bseg * 8;
        rb0 = *(const float4*)p; rb1 = *(const float4*)(p + 4);
    };
    auto stStage = [&](int buf) {
        float* a = As + buf * 64 * 20 + am * 20 + aq * 4;
        a[0]=wmma::__float_to_tf32(ra.x); a[1]=wmma::__float_to_tf32(ra.y);
        a[2]=wmma::__float_to_tf32(ra.z); a[3]=wmma::__float_to_tf32(ra.w);
        float* b = Bs + buf * 16 * 136 + br * 136 + bseg * 8;
        b[0]=wmma::__float_to_tf32(rb0.x); b[1]=wmma::__float_to_tf32(rb0.y);
        b[2]=wmma::__float_to_tf32(rb0.z); b[3]=wmma::__float_to_tf32(rb0.w);
        b[4]=wmma::__float_to_tf32(rb1.x); b[5]=wmma::__float_to_tf32(rb1.y);
        b[6]=wmma::__float_to_tf32(rb1.z); b[7]=wmma::__float_to_tf32(rb1.w);
    };

    ldA(0); ldB(0); stStage(0); __syncthreads();
    const int NIT = NH / 16;
    for (int it = 0; it < NIT; it++) {
        int buf = it & 1;
        if (it < NIT - 1) { ldA((it + 1) * 16); ldB((it + 1) * 16); }
#pragma unroll
        for (int ks = 0; ks < 2; ks++) {
            wmma::fragment<wmma::matrix_a, 16, 16, 8, wmma::precision::tf32, wmma::row_major> af[2];
            wmma::fragment<wmma::matrix_b, 16, 16, 8, wmma::precision::tf32, wmma::row_major> bf[2];
#pragma unroll
            for (int i = 0; i < 2; i++)
                wmma::load_matrix_sync(af[i], As + buf*64*20 + (wm*32 + i*16)*20 + ks*8, 20);
#pragma unroll
            for (int j = 0; j < 2; j++)
                wmma::load_matrix_sync(bf[j], Bs + buf*16*136 + ks*8*136 + wn*32 + j*16, 136);
#pragma unroll
            for (int i = 0; i < 2; i++)
#pragma unroll
                for (int j = 0; j < 2; j++) wmma::mma_sync(acc[i][j], af[i], bf[j], acc[i][j]);
        }
        if (it < NIT - 1) stStage(buf ^ 1);
        __syncthreads();
    }
#pragma unroll
    for (int i = 0; i < 2; i++)
#pragma unroll
        for (int j = 0; j < 2; j++)
            wmma::store_matrix_sync(Cs + (wm*32 + i*16)*132 + wn*32 + j*16,
                                    acc[i][j], 132, wmma::mem_row_major);
    __syncthreads();
    {
        int b = tid >> 2, seg = tid & 3;
#pragma unroll
        for (int k = 0; k < 32; k++)
            g_wa[b * NH + n0 + seg * 32 + k] = Cs[b * 132 + seg * 32 + k];
    }
}

// ============================================================
// 3: fused attention GEMM — A-resident bf16 wmma, 32-row CTAs
// Grid 2048: CTA = (t, half-batch). A = 32x1024 bf16 resident.
// 4 n0-chunks of 256 cols; B double-buffered LDG->regs->STS.
// 128 thr / 4 warps; warp tile 32x64 (acc 2x4). 2 CTAs/SM.
// ============================================================
#define AT_LDA 1032
#define AT_BLD 264
#define AT_SA_BYTES (32 * AT_LDA * 2)          // 66048
#define AT_SB_BYTES (2 * 32 * AT_BLD * 2)      // 33792
#define AT_SC_BYTES (4 * 16 * 36 * 4)          // 9216
#define AT_SMEM (AT_SA_BYTES + AT_SB_BYTES + AT_SC_BYTES)  // 109056

__global__ __launch_bounds__(128) void k_att(const float* __restrict__ mem,
                                             const float* __restrict__ attV) {
    extern __shared__ __align__(16) char dyn[];
    __nv_bfloat16* sA = (__nv_bfloat16*)dyn;
    __nv_bfloat16* sB = (__nv_bfloat16*)(dyn + AT_SA_BYTES);
    float* scratch   = (float*)(dyn + AT_SA_BYTES + AT_SB_BYTES);

    const int row0 = blockIdx.x * 32;          // global row in (t*64+b) space
    const int b0   = (blockIdx.x & 1) * 32;    // batch base for this CTA
    const int tid  = threadIdx.x;
    const int wid  = tid >> 5;                 // 0..3
    const int lane = tid & 31;
    const int wn   = wid;                      // 64-col strip within 256 chunk

    // ---- load A panel once: 32x1024 fp32 -> bf16 smem ----
#pragma unroll 8
    for (int i = 0; i < 64; i++) {
        int idx = tid + i * 128;               // float4 index within 32x256
        int r = idx >> 8, c4 = idx & 255;
        float4 v = *(const float4*)(mem + (size_t)(row0 + r) * NH + c4 * 4);
        __nv_bfloat162 h0 = __float22bfloat162_rn(make_float2(v.x, v.y));
        __nv_bfloat162 h1 = __float22bfloat162_rn(make_float2(v.z, v.w));
        uint2 u; u.x = *(unsigned*)&h0; u.y = *(unsigned*)&h1;
        *(uint2*)&sA[r * AT_LDA + c4 * 4] = u;
    }
    __syncthreads();

    float pAcc[2] = {0.0f, 0.0f};
    const int r    = lane >> 1;
    const int half = lane & 1;

    uint4 rB[8];
    auto ldB = [&](int n0, int kt) {
        const __nv_bfloat16* base = g_Uh + (size_t)(kt * 32) * NH + n0 * 256;
#pragma unroll
        for (int i = 0; i < 8; i++) {
            int idx = tid + i * 128;           // uint4 index within 32x32
            int rr = idx >> 5, cc = idx & 31;
            rB[i] = *(const uint4*)(base + (size_t)rr * NH + cc * 8);
        }
    };
    auto stB = [&](int buf) {
#pragma unroll
        for (int i = 0; i < 8; i++) {
            int idx = tid + i * 128;
            int rr = idx >> 5, cc = idx & 31;
            *(uint4*)&sB[buf * 32 * AT_BLD + rr * AT_BLD + cc * 8] = rB[i];
        }
    };

    for (int n0 = 0; n0 < 4; n0++) {
        wmma::fragment<wmma::accumulator, 16, 16, 16, float> acc[2][4];
#pragma unroll
        for (int i = 0; i < 2; i++)
#pragma unroll
            for (int j = 0; j < 4; j++) wmma::fill_fragment(acc[i][j], 0.0f);

        ldB(n0, 0); stB(0); __syncthreads();
        for (int kt = 0; kt < 32; kt++) {
            int buf = kt & 1;
            if (kt < 31) ldB(n0, kt + 1);
#pragma unroll
            for (int ks = 0; ks < 2; ks++) {
                wmma::fragment<wmma::matrix_a, 16, 16, 16, __nv_bfloat16, wmma::row_major> af[2];
                wmma::fragment<wmma::matrix_b, 16, 16, 16, __nv_bfloat16, wmma::row_major> bf[4];
#pragma unroll
                for (int i = 0; i < 2; i++)
                    wmma::load_matrix_sync(af[i], &sA[(i*16) * AT_LDA + kt*32 + ks*16], AT_LDA);
#pragma unroll
                for (int j = 0; j < 4; j++)
                    wmma::load_matrix_sync(bf[j], &sB[buf*32*AT_BLD + ks*16*AT_BLD + wn*64 + j*16], AT_BLD);
#pragma unroll
                for (int i = 0; i < 2; i++)
#pragma unroll
                    for (int j = 0; j < 4; j++) wmma::mma_sync(acc[i][j], af[i], bf[j], acc[i][j]);
            }
            if (kt < 31) stB(buf ^ 1);
            __syncthreads();
        }

        // epilogue for chunk n0: tanh + attV dot, 16x36 per-warp scratch
        float* sc = scratch + wid * (16 * 36);
#pragma unroll
        for (int i = 0; i < 2; i++) {
            int b = b0 + i * 16 + r;
#pragma unroll
            for (int jh = 0; jh < 2; jh++) {
                wmma::store_matrix_sync(sc,      acc[i][jh*2],   36, wmma::mem_row_major);
                wmma::store_matrix_sync(sc + 16, acc[i][jh*2+1], 36, wmma::mem_row_major);
                __syncwarp();
                int colbase = n0 * 256 + wn * 64 + jh * 32 + half * 16;
                const float* crow = sc + r * 36 + half * 16;
                const float* wap  = g_wa + (size_t)b * NH + colbase;
                const float* avp  = attV + colbase;
                float p = 0.0f;
#pragma unroll
                for (int q = 0; q < 4; q++) {
                    float4 av = *(const float4*)(avp + q * 4);
                    float4 wa = *(const float4*)(wap + q * 4);
                    p += av.x * tanh_approx(crow[q*4+0] + wa.x);
                    p += av.y * tanh_approx(crow[q*4+1] + wa.y);
                    p += av.z * tanh_approx(crow[q*4+2] + wa.z);
                    p += av.w * tanh_approx(crow[q*4+3] + wa.w);
                }
                __syncwarp();
                p += __shfl_down_sync(0xffffffffu, p, 1);
                if (half == 0) pAcc[i] += p;
            }
        }
        __syncthreads();
    }

    if (half == 0) {
#pragma unroll
        for (int i = 0; i < 2; i++)
            atomicAdd(&g_score[row0 + i * 16 + r], pAcc[i]);
    }
}

// ---------------- 4: softmax over t ----------------
__global__ void k_softmax() {
    int b = blockIdx.x;
    int tid = threadIdx.x;
    __shared__ float red[256];
    float vals[4];
    float mx = -1e30f;
#pragma unroll
    for (int i = 0; i < 4; i++) {
        vals[i] = g_score[(tid + i * 256) * BB + b];
        mx = fmaxf(mx, vals[i]);
    }
    red[tid] = mx; __syncthreads();
    for (int s = 128; s > 0; s >>= 1) {
        if (tid < s) red[tid] = fmaxf(red[tid], red[tid + s]);
        __syncthreads();
    }
    mx = red[0]; __syncthreads();
    float sum = 0.0f;
#pragma unroll
    for (int i = 0; i < 4; i++) { vals[i] = expf(vals[i] - mx); sum += vals[i]; }
    red[tid] = sum; __syncthreads();
    for (int s = 128; s > 0; s >>= 1) {
        if (tid < s) red[tid] += red[tid + s];
        __syncthreads();
    }
    float inv = 1.0f / red[0];
#pragma unroll
    for (int i = 0; i < 4; i++)
        g_score[(tid + i * 256) * BB + b] = vals[i] * inv;
}

// ---------------- 5: context ----------------
__global__ void k_ctx(const float* __restrict__ mem) {
    int b = blockIdx.y;
    int j = blockIdx.x * 256 + threadIdx.x;
    __shared__ float w[TT];
    for (int t = threadIdx.x; t < TT; t += 256) w[t] = g_score[t * BB + b];
    __syncthreads();
    float acc = 0.0f;
#pragma unroll 4
    for (int t = 0; t < TT; t++)
        acc += w[t] * mem[((size_t)t * BB + b) * NH + j];
    g_ctx[b * NH + j] = acc;
}

// ============================================================
// 6: gates split-K (grid 64 x 3) — tf32 wmma
// ============================================================
__global__ __launch_bounds__(256) void k_gates(const float* __restrict__ h_prev,
                                               const float* __restrict__ W_ih,
                                               const float* __restrict__ W_hh) {
    __shared__ float sm[8448];
    float* As = sm;
    float* Bs = sm + 2 * 64 * 20;
    float* Cs = sm;

    const int n0   = blockIdx.x * 128;
    const int part = blockIdx.y;
    const int tid  = threadIdx.x;
    const int wid  = tid >> 5;
    const int wm   = wid >> 2, wn = wid & 3;

    const float* Asrc = (part == 0) ? g_emb : (part == 1) ? h_prev : g_ctx;
    const float* Bsrc = (part == 0) ? W_ih  : (W_hh + (part == 2 ? (size_t)1024 * G4 : 0));
    float* outp = g_gp[part];

    wmma::fragment<wmma::accumulator, 16, 16, 8, float> acc[2][2];
#pragma unroll
    for (int i = 0; i < 2; i++)
#pragma unroll
        for (int j = 0; j < 2; j++) wmma::fill_fragment(acc[i][j], 0.0f);

    const int am = tid >> 2, aq = tid & 3;
    const int br = tid >> 4, bseg = tid & 15;

    float4 ra, rb0, rb1;
    auto ldA = [&](int k0) { ra = *(const float4*)(Asrc + am * 1024 + k0 + aq * 4); };
    auto ldB = [&](int k0) {
        const float* p = Bsrc + (size_t)(k0 + br) * G4 + n0 + bseg * 8;
        rb0 = *(const float4*)p; rb1 = *(const float4*)(p + 4);
    };
    auto stStage = [&](int buf) {
        float* a = As + buf * 64 * 20 + am * 20 + aq * 4;
        a[0]=wmma::__float_to_tf32(ra.x); a[1]=wmma::__float_to_tf32(ra.y);
        a[2]=wmma::__float_to_tf32(ra.z); a[3]=wmma::__float_to_tf32(ra.w);
        float* b = Bs + buf * 16 * 136 + br * 136 + bseg * 8;
        b[0]=wmma::__float_to_tf32(rb0.x); b[1]=wmma::__float_to_tf32(rb0.y);
        b[2]=wmma::__float_to_tf32(rb0.z); b[3]=wmma::__float_to_tf32(rb0.w);
        b[4]=wmma::__float_to_tf32(rb1.x); b[5]=wmma::__float_to_tf32(rb1.y);
        b[6]=wmma::__float_to_tf32(rb1.z); b[7]=wmma::__float_to_tf32(rb1.w);
    };

    ldA(0); ldB(0); stStage(0); __syncthreads();
    const int NIT = 1024 / 16;
    for (int it = 0; it < NIT; it++) {
        int buf = it & 1;
        if (it < NIT - 1) { ldA((it + 1) * 16); ldB((it + 1) * 16); }
#pragma unroll
        for (int ks = 0; ks < 2; ks++) {
            wmma::fragment<wmma::matrix_a, 16, 16, 8, wmma::precision::tf32, wmma::row_major> af[2];
            wmma::fragment<wmma::matrix_b, 16, 16, 8, wmma::precision::tf32, wmma::row_major> bf[2];
#pragma unroll
            for (int i = 0; i < 2; i++)
                wmma::load_matrix_sync(af[i], As + buf*64*20 + (wm*32 + i*16)*20 + ks*8, 20);
#pragma unroll
            for (int j = 0; j < 2; j++)
                wmma::load_matrix_sync(bf[j], Bs + buf*16*136 + ks*8*136 + wn*32 + j*16, 136);
#pragma unroll
            for (int i = 0; i < 2; i++)
#pragma unroll
                for (int j = 0; j < 2; j++) wmma::mma_sync(acc[i][j], af[i], bf[j], acc[i][j]);
        }
        if (it < NIT - 1) stStage(buf ^ 1);
        __syncthreads();
    }
#pragma unroll
    for (int i = 0; i < 2; i++)
#pragma unroll
        for (int j = 0; j < 2; j++)
            wmma::store_matrix_sync(Cs + (wm*32 + i*16)*132 + wn*32 + j*16,
                                    acc[i][j], 132, wmma::mem_row_major);
    __syncthreads();
    {
        int b = tid >> 2, seg = tid & 3;
#pragma unroll
        for (int k = 0; k < 32; k++)
            outp[(size_t)b * G4 + n0 + seg * 32 + k] = Cs[b * 132 + seg * 32 + k];
    }
}

// ---------------- 7: LSTM elementwise ----------------
__global__ void k_lstm(const float* __restrict__ c_prev,
                       const float* __restrict__ b_lstm,
                       float* __restrict__ out_ht,
                       float* __restrict__ out_ct) {
    int idx = blockIdx.x * 256 + threadIdx.x;
    int b = idx >> 11, n = idx & 2047;
    const float* g0 = g_gp[0] + (size_t)b * G4;
    const float* g1 = g_gp[1] + (size_t)b * G4;
    const float* g2 = g_gp[2] + (size_t)b * G4;
    float i_ = g0[n]        + g1[n]        + g2[n]        + b_lstm[n];
    float f_ = g0[n + 2048] + g1[n + 2048] + g2[n + 2048] + b_lstm[n + 2048];
    float gg = g0[n + 4096] + g1[n + 4096] + g2[n + 4096] + b_lstm[n + 4096];
    float o_ = g0[n + 6144] + g1[n + 6144] + g2[n + 6144] + b_lstm[n + 6144];
    float c = sigmoid_acc(f_) * c_prev[idx] + sigmoid_acc(i_) * tanhf(gg);
    out_ct[idx] = c;
    float h = sigmoid_acc(o_) * tanhf(c);
    if (n < 1024) out_ht[b * 1024 + n] = h;
}

// ============================================================
// 8: decoded = ht @ dec_w^T + dec_b — tf32 wmma
// ============================================================
__global__ __launch_bounds__(256) void k_dec(const float* __restrict__ dec_w,
                                             const float* __restrict__ dec_b,
                                             const float* __restrict__ ht,
                                             float* __restrict__ out) {
    __shared__ float sm[8448];
    float* As  = sm;
    float* Bs  = sm + 2 * 128 * 20;
    float* CsT = sm;

    const int v0  = blockIdx.x * 128;
    const int tid = threadIdx.x;
    const int wid = tid >> 5;
    const int wm  = wid >> 1, wn = wid & 1;

    wmma::fragment<wmma::accumulator, 16, 16, 8, float> acc[2][2];
#pragma unroll
    for (int i = 0; i < 2; i++)
#pragma unroll
        for (int j = 0; j < 2; j++) wmma::fill_fragment(acc[i][j], 0.0f);

    const int ar = tid >> 1, ah = tid & 1;
    const int bb = tid >> 2, bq = tid & 3;

    float4 ra0, ra1, rb;
    auto ldA = [&](int k0) {
        if (v0 + ar < NVOC) {
            const float* p = dec_w + (size_t)(v0 + ar) * 1024 + k0 + ah * 8;
            ra0 = *(const float4*)p; ra1 = *(const float4*)(p + 4);
        } else {
            ra0 = make_float4(0,0,0,0); ra1 = ra0;
        }
    };
    auto ldB = [&](int k0) { rb = *(const float4*)(ht + bb * 1024 + k0 + bq * 4); };
    auto stStage = [&](int buf) {
        float* a = As + buf * 128 * 20 + ar * 20 + ah * 8;
        a[0]=wmma::__float_to_tf32(ra0.x); a[1]=wmma::__float_to_tf32(ra0.y);
        a[2]=wmma::__float_to_tf32(ra0.z); a[3]=wmma::__float_to_tf32(ra0.w);
        a[4]=wmma::__float_to_tf32(ra1.x); a[5]=wmma::__float_to_tf32(ra1.y);
        a[6]=wmma::__float_to_tf32(ra1.z); a[7]=wmma::__float_to_tf32(ra1.w);
        float* b = Bs + buf * 64 * 20 + bb * 20 + bq * 4;
        b[0]=wmma::__float_to_tf32(rb.x); b[1]=wmma::__float_to_tf32(rb.y);
        b[2]=wmma::__float_to_tf32(rb.z); b[3]=wmma::__float_to_tf32(rb.w);
    };

    ldA(0); ldB(0); stStage(0); __syncthreads();
    for (int it = 0; it < 64; it++) {
        int buf = it & 1;
        if (it < 63) { ldA((it + 1) * 16); ldB((it + 1) * 16); }
#pragma unroll
        for (int ks = 0; ks < 2; ks++) {
            wmma::fragment<wmma::matrix_a, 16, 16, 8, wmma::precision::tf32, wmma::row_major> af[2];
            wmma::fragment<wmma::matrix_b, 16, 16, 8, wmma::precision::tf32, wmma::col_major> bf[2];
#pragma unroll
            for (int i = 0; i < 2; i++)
                wmma::load_matrix_sync(af[i], As + buf*128*20 + (wm*32 + i*16)*20 + ks*8, 20);
#pragma unroll
            for (int j = 0; j < 2; j++)
                wmma::load_matrix_sync(bf[j], Bs + buf*64*20 + (wn*32 + j*16)*20 + ks*8, 20);
#pragma unroll
            for (int i = 0; i < 2; i++)
#pragma unroll
                for (int j = 0; j < 2; j++) wmma::mma_sync(acc[i][j], af[i], bf[j], acc[i][j]);
        }
        if (it < 63) stStage(buf ^ 1);
        __syncthreads();
    }
#pragma unroll
    for (int i = 0; i < 2; i++)
#pragma unroll
        for (int j = 0; j < 2; j++)
            wmma::store_matrix_sync(CsT + (wn*32 + j*16)*132 + wm*32 + i*16,
                                    acc[i][j], 132, wmma::mem_col_major);
    __syncthreads();
    {
        int b = tid >> 2, seg = tid & 3;
#pragma unroll
        for (int k = 0; k < 32; k++) {
            int v = v0 + seg * 32 + k;
            if (v < NVOC)
                out[(size_t)b * NVOC + v] = CsT[b * 132 + seg * 32 + k] + __ldg(dec_b + v);
        }
    }
}

// ---------------- launch ----------------
extern "C" void kernel_launch(void* const* d_in, const int* in_sizes, int n_in,
                              void* d_out, int out_size) {
    const int*   inputs   = (const int*)  d_in[0];
    const float* mem      = (const float*)d_in[1];
    const float* h_prev   = (const float*)d_in[2];
    const float* c_prev   = (const float*)d_in[3];
    const float* enc_w    = (const float*)d_in[4];
    const float* attWa    = (const float*)d_in[5];
    const float* attUa    = (const float*)d_in[6];
    const float* attV     = (const float*)d_in[7];
    const float* W_ih     = (const float*)d_in[8];
    const float* W_hh     = (const float*)d_in[9];
    const float* b_lstm   = (const float*)d_in[10];
    const float* dec_w    = (const float*)d_in[11];
    const float* dec_b    = (const float*)d_in[12];

    float* out      = (float*)d_out;
    float* out_dec  = out;
    float* out_ht   = out + (size_t)BB * NVOC;
    float* out_ct   = out_ht + (size_t)BB * NH;

    // unconditional + idempotent: identical work on every call (no static guard)
    cudaFuncSetAttribute(k_att, cudaFuncAttributeMaxDynamicSharedMemorySize, AT_SMEM);

    k_pre<<<1280, 256>>>(inputs, enc_w, attUa);
    k_wa<<<8, 256>>>(h_prev, attWa);
    k_att<<<2048, 128, AT_SMEM>>>(mem, attV);
    k_softmax<<<64, 256>>>();
    k_ctx<<<dim3(4, 64), 256>>>(mem);
    k_gates<<<dim3(64, 3), 256>>>(h_prev, W_ih, W_hh);
    k_lstm<<<(BB * H2) / 256, 256>>>(c_prev, b_lstm, out_ht, out_ct);
    k_dec<<<(NVOC + 127) / 128, 256>>>(dec_w, dec_b, out_ht, out_dec);
}

// round 14
// speedup vs baseline: 1.1256x; 1.1256x over previous
#include <cuda_runtime.h>
#include <cuda_bf16.h>
#include <mma.h>
#include <math.h>
#include <stdint.h>

using namespace nvcuda;

#define NVOC 50257
#define NIN  1024
#define NH   1024
#define H2   2048
#define G4   8192
#define BB   64
#define TT   1024

// ---------------- scratch ----------------
__device__ float g_wa[BB*NH];
__device__ float g_score[TT*BB];
__device__ float g_ctx[BB*NH];
__device__ float g_emb[BB*NIN];
__device__ float g_gp[3][BB*G4];
__device__ __nv_bfloat16 g_Uh[NH*NH];   // attUa in bf16, [k][n] layout

__device__ __forceinline__ float tanh_approx(float x) {
    float y; asm("tanh.approx.f32 %0, %1;" : "=f"(y) : "f"(x)); return y;
}
__device__ __forceinline__ float sigmoid_acc(float x) {
    return 1.0f / (1.0f + expf(-x));
}

// ---------------- 1: zero score + gather emb + convert attUa (merged) -------
__global__ void k_pre(const int* __restrict__ inputs,
                      const float* __restrict__ enc_w,
                      const float* __restrict__ attUa) {
    int idx = blockIdx.x * blockDim.x + threadIdx.x;   // 0..327679
    if (idx < 65536) {
        g_score[idx] = 0.0f;
        int b = idx >> 10, c = idx & 1023;
        g_emb[idx] = enc_w[(size_t)inputs[b] * NIN + c];
    } else {
        int q = idx - 65536;                           // float4 index, 262144
        float4 v = *(const float4*)(attUa + (size_t)q * 4);
        __nv_bfloat162 h0 = __float22bfloat162_rn(make_float2(v.x, v.y));
        __nv_bfloat162 h1 = __float22bfloat162_rn(make_float2(v.z, v.w));
        uint2 u; u.x = *(unsigned*)&h0; u.y = *(unsigned*)&h1;
        *(uint2*)&g_Uh[(size_t)q * 4] = u;
    }
}

// ============================================================
// 2: wa = h_prev @ attWa   (64 x 1024, K=1024) — tf32 wmma
// ============================================================
__global__ __launch_bounds__(256) void k_wa(const float* __restrict__ h_prev,
                                            const float* __restrict__ attWa) {
    __shared__ float sm[8448];
    float* As = sm;
    float* Bs = sm + 2 * 64 * 20;
    float* Cs = sm;

    const int n0  = blockIdx.x * 128;
    const int tid = threadIdx.x;
    const int wid = tid >> 5;
    const int wm  = wid >> 2, wn = wid & 3;

    wmma::fragment<wmma::accumulator, 16, 16, 8, float> acc[2][2];
#pragma unroll
    for (int i = 0; i < 2; i++)
#pragma unroll
        for (int j = 0; j < 2; j++) wmma::fill_fragment(acc[i][j], 0.0f);

    const int am = tid >> 2, aq = tid & 3;
    const int br = tid >> 4, bseg = tid & 15;

    float4 ra, rb0, rb1;
    auto ldA = [&](int k0) { ra = *(const float4*)(h_prev + am * NH + k0 + aq * 4); };
    auto ldB = [&](int k0) {
        const float* p = attWa + (size_t)(k0 + br) * NH + n0 + bseg * 8;
        rb0 = *(const float4*)p; rb1 = *(const float4*)(p + 4);
    };
    auto stStage = [&](int buf) {
        float* a = As + buf * 64 * 20 + am * 20 + aq * 4;
        a[0]=wmma::__float_to_tf32(ra.x); a[1]=wmma::__float_to_tf32(ra.y);
        a[2]=wmma::__float_to_tf32(ra.z); a[3]=wmma::__float_to_tf32(ra.w);
        float* b = Bs + buf * 16 * 136 + br * 136 + bseg * 8;
        b[0]=wmma::__float_to_tf32(rb0.x); b[1]=wmma::__float_to_tf32(rb0.y);
        b[2]=wmma::__float_to_tf32(rb0.z); b[3]=wmma::__float_to_tf32(rb0.w);
        b[4]=wmma::__float_to_tf32(rb1.x); b[5]=wmma::__float_to_tf32(rb1.y);
        b[6]=wmma::__float_to_tf32(rb1.z); b[7]=wmma::__float_to_tf32(rb1.w);
    };

    ldA(0); ldB(0); stStage(0); __syncthreads();
    const int NIT = NH / 16;
    for (int it = 0; it < NIT; it++) {
        int buf = it & 1;
        if (it < NIT - 1) { ldA((it + 1) * 16); ldB((it + 1) * 16); }
#pragma unroll
        for (int ks = 0; ks < 2; ks++) {
            wmma::fragment<wmma::matrix_a, 16, 16, 8, wmma::precision::tf32, wmma::row_major> af[2];
            wmma::fragment<wmma::matrix_b, 16, 16, 8, wmma::precision::tf32, wmma::row_major> bf[2];
#pragma unroll
            for (int i = 0; i < 2; i++)
                wmma::load_matrix_sync(af[i], As + buf*64*20 + (wm*32 + i*16)*20 + ks*8, 20);
#pragma unroll
            for (int j = 0; j < 2; j++)
                wmma::load_matrix_sync(bf[j], Bs + buf*16*136 + ks*8*136 + wn*32 + j*16, 136);
#pragma unroll
            for (int i = 0; i < 2; i++)
#pragma unroll
                for (int j = 0; j < 2; j++) wmma::mma_sync(acc[i][j], af[i], bf[j], acc[i][j]);
        }
        if (it < NIT - 1) stStage(buf ^ 1);
        __syncthreads();
    }
#pragma unroll
    for (int i = 0; i < 2; i++)
#pragma unroll
        for (int j = 0; j < 2; j++)
            wmma::store_matrix_sync(Cs + (wm*32 + i*16)*132 + wn*32 + j*16,
                                    acc[i][j], 132, wmma::mem_row_major);
    __syncthreads();
    {
        int b = tid >> 2, seg = tid & 3;
#pragma unroll
        for (int k = 0; k < 32; k++)
            g_wa[b * NH + n0 + seg * 32 + k] = Cs[b * 132 + seg * 32 + k];
    }
}

// ============================================================
// 3: fused attention GEMM — A-resident bf16 wmma, 64x64 warp tiles
// One CTA per timestep t: A = mem[t] (64x1024) bf16 resident.
// 2 passes of 512 cols; 8 warps 1x8 (each warp: 64 rows x 64 cols).
// B double-buffered LDG->regs->STS, 32-k steps. bf loaded singly.
// ============================================================
#define AT_LDA 1032                            // A row stride (bf16)
#define AT_BLD 520                             // B row stride (bf16): 512+8
#define AT_SA_BYTES (64 * AT_LDA * 2)          // 132096
#define AT_SB_BYTES (2 * 32 * AT_BLD * 2)      // 66560
#define AT_SC_BYTES (8 * 16 * 36 * 4)          // 18432
#define AT_SMEM (AT_SA_BYTES + AT_SB_BYTES + AT_SC_BYTES)  // 217088

__global__ __launch_bounds__(256) void k_att(const float* __restrict__ mem,
                                             const float* __restrict__ attV) {
    extern __shared__ __align__(16) char dyn[];
    __nv_bfloat16* sA = (__nv_bfloat16*)dyn;
    __nv_bfloat16* sB = (__nv_bfloat16*)(dyn + AT_SA_BYTES);
    float* scratch   = (float*)(dyn + AT_SA_BYTES + AT_SB_BYTES);

    const int row0 = blockIdx.x * 64;          // = t*64
    const int tid  = threadIdx.x;
    const int wid  = tid >> 5;                 // 0..7 = 64-col strip
    const int lane = tid & 31;

    // ---- load A panel once: 64x1024 fp32 -> bf16 smem ----
#pragma unroll 8
    for (int i = 0; i < 64; i++) {
        int idx = tid + i * 256;               // float4 index within 64x256
        int r = idx >> 8, c4 = idx & 255;
        float4 v = *(const float4*)(mem + (size_t)(row0 + r) * NH + c4 * 4);
        __nv_bfloat162 h0 = __float22bfloat162_rn(make_float2(v.x, v.y));
        __nv_bfloat162 h1 = __float22bfloat162_rn(make_float2(v.z, v.w));
        uint2 u; u.x = *(unsigned*)&h0; u.y = *(unsigned*)&h1;
        *(uint2*)&sA[r * AT_LDA + c4 * 4] = u;
    }
    __syncthreads();

    float pAcc[4] = {0.0f, 0.0f, 0.0f, 0.0f};
    const int r    = lane >> 1;
    const int half = lane & 1;

    uint4 rB[8];
    auto ldB = [&](int p, int kt) {            // B tile: 32 k-rows x 512 n
        const __nv_bfloat16* base = g_Uh + (size_t)(kt * 32) * NH + p * 512;
#pragma unroll
        for (int i = 0; i < 8; i++) {
            int idx = tid + i * 256;           // 0..2047: rr (32) x cc (64)
            int rr = idx >> 6, cc = idx & 63;
            rB[i] = *(const uint4*)(base + (size_t)rr * NH + cc * 8);
        }
    };
    auto stB = [&](int buf) {
#pragma unroll
        for (int i = 0; i < 8; i++) {
            int idx = tid + i * 256;
            int rr = idx >> 6, cc = idx & 63;
            *(uint4*)&sB[buf * 32 * AT_BLD + rr * AT_BLD + cc * 8] = rB[i];
        }
    };

    for (int p = 0; p < 2; p++) {
        wmma::fragment<wmma::accumulator, 16, 16, 16, float> acc[4][4];
#pragma unroll
        for (int i = 0; i < 4; i++)
#pragma unroll
            for (int j = 0; j < 4; j++) wmma::fill_fragment(acc[i][j], 0.0f);

        ldB(p, 0); stB(0); __syncthreads();
        for (int kt = 0; kt < 32; kt++) {
            int buf = kt & 1;
            if (kt < 31) ldB(p, kt + 1);
#pragma unroll
            for (int ks = 0; ks < 2; ks++) {
                wmma::fragment<wmma::matrix_a, 16, 16, 16, __nv_bfloat16, wmma::row_major> af[4];
#pragma unroll
                for (int i = 0; i < 4; i++)
                    wmma::load_matrix_sync(af[i], &sA[(i*16) * AT_LDA + kt*32 + ks*16], AT_LDA);
#pragma unroll
                for (int j = 0; j < 4; j++) {
                    wmma::fragment<wmma::matrix_b, 16, 16, 16, __nv_bfloat16, wmma::row_major> bf;
                    wmma::load_matrix_sync(bf, &sB[buf*32*AT_BLD + ks*16*AT_BLD + wid*64 + j*16], AT_BLD);
#pragma unroll
                    for (int i = 0; i < 4; i++)
                        wmma::mma_sync(acc[i][j], af[i], bf, acc[i][j]);
                }
            }
            if (kt < 31) stB(buf ^ 1);
            __syncthreads();
        }

        // epilogue for pass p: tanh + attV dot, 16x36 per-warp scratch
        float* sc = scratch + wid * (16 * 36);
#pragma unroll
        for (int i = 0; i < 4; i++) {
            int b = i * 16 + r;                // batch row (CTA covers one t)
#pragma unroll
            for (int jh = 0; jh < 2; jh++) {
                wmma::store_matrix_sync(sc,      acc[i][jh*2],   36, wmma::mem_row_major);
                wmma::store_matrix_sync(sc + 16, acc[i][jh*2+1], 36, wmma::mem_row_major);
                __syncwarp();
                int colbase = p * 512 + wid * 64 + jh * 32 + half * 16;
                const float* crow = sc + r * 36 + half * 16;
                const float* wap  = g_wa + (size_t)b * NH + colbase;
                const float* avp  = attV + colbase;
                float pv = 0.0f;
#pragma unroll
                for (int q = 0; q < 4; q++) {
                    float4 av = *(const float4*)(avp + q * 4);
                    float4 wa = *(const float4*)(wap + q * 4);
                    pv += av.x * tanh_approx(crow[q*4+0] + wa.x);
                    pv += av.y * tanh_approx(crow[q*4+1] + wa.y);
                    pv += av.z * tanh_approx(crow[q*4+2] + wa.z);
                    pv += av.w * tanh_approx(crow[q*4+3] + wa.w);
                }
                __syncwarp();
                pv += __shfl_down_sync(0xffffffffu, pv, 1);
                if (half == 0) pAcc[i] += pv;
            }
        }
        __syncthreads();
    }

    if (half == 0) {
#pragma unroll
        for (int i = 0; i < 4; i++)
            atomicAdd(&g_score[row0 + i * 16 + r], pAcc[i]);
    }
}

// ---------------- 4: softmax over t ----------------
__global__ void k_softmax() {
    int b = blockIdx.x;
    int tid = threadIdx.x;
    __shared__ float red[256];
    float vals[4];
    float mx = -1e30f;
#pragma unroll
    for (int i = 0; i < 4; i++) {
        vals[i] = g_score[(tid + i * 256) * BB + b];
        mx = fmaxf(mx, vals[i]);
    }
    red[tid] = mx; __syncthreads();
    for (int s = 128; s > 0; s >>= 1) {
        if (tid < s) red[tid] = fmaxf(red[tid], red[tid + s]);
        __syncthreads();
    }
    mx = red[0]; __syncthreads();
    float sum = 0.0f;
#pragma unroll
    for (int i = 0; i < 4; i++) { vals[i] = expf(vals[i] - mx); sum += vals[i]; }
    red[tid] = sum; __syncthreads();
    for (int s = 128; s > 0; s >>= 1) {
        if (tid < s) red[tid] += red[tid + s];
        __syncthreads();
    }
    float inv = 1.0f / red[0];
#pragma unroll
    for (int i = 0; i < 4; i++)
        g_score[(tid + i * 256) * BB + b] = vals[i] * inv;
}

// ---------------- 5: context ----------------
__global__ void k_ctx(const float* __restrict__ mem) {
    int b = blockIdx.y;
    int j = blockIdx.x * 256 + threadIdx.x;
    __shared__ float w[TT];
    for (int t = threadIdx.x; t < TT; t += 256) w[t] = g_score[t * BB + b];
    __syncthreads();
    float acc = 0.0f;
#pragma unroll 4
    for (int t = 0; t < TT; t++)
        acc += w[t] * mem[((size_t)t * BB + b) * NH + j];
    g_ctx[b * NH + j] = acc;
}

// ============================================================
// 6: gates split-K (grid 64 x 3) — tf32 wmma
// ============================================================
__global__ __launch_bounds__(256) void k_gates(const float* __restrict__ h_prev,
                                               const float* __restrict__ W_ih,
                                               const float* __restrict__ W_hh) {
    __shared__ float sm[8448];
    float* As = sm;
    float* Bs = sm + 2 * 64 * 20;
    float* Cs = sm;

    const int n0   = blockIdx.x * 128;
    const int part = blockIdx.y;
    const int tid  = threadIdx.x;
    const int wid  = tid >> 5;
    const int wm   = wid >> 2, wn = wid & 3;

    const float* Asrc = (part == 0) ? g_emb : (part == 1) ? h_prev : g_ctx;
    const float* Bsrc = (part == 0) ? W_ih  : (W_hh + (part == 2 ? (size_t)1024 * G4 : 0));
    float* outp = g_gp[part];

    wmma::fragment<wmma::accumulator, 16, 16, 8, float> acc[2][2];
#pragma unroll
    for (int i = 0; i < 2; i++)
#pragma unroll
        for (int j = 0; j < 2; j++) wmma::fill_fragment(acc[i][j], 0.0f);

    const int am = tid >> 2, aq = tid & 3;
    const int br = tid >> 4, bseg = tid & 15;

    float4 ra, rb0, rb1;
    auto ldA = [&](int k0) { ra = *(const float4*)(Asrc + am * 1024 + k0 + aq * 4); };
    auto ldB = [&](int k0) {
        const float* p = Bsrc + (size_t)(k0 + br) * G4 + n0 + bseg * 8;
        rb0 = *(const float4*)p; rb1 = *(const float4*)(p + 4);
    };
    auto stStage = [&](int buf) {
        float* a = As + buf * 64 * 20 + am * 20 + aq * 4;
        a[0]=wmma::__float_to_tf32(ra.x); a[1]=wmma::__float_to_tf32(ra.y);
        a[2]=wmma::__float_to_tf32(ra.z); a[3]=wmma::__float_to_tf32(ra.w);
        float* b = Bs + buf * 16 * 136 + br * 136 + bseg * 8;
        b[0]=wmma::__float_to_tf32(rb0.x); b[1]=wmma::__float_to_tf32(rb0.y);
        b[2]=wmma::__float_to_tf32(rb0.z); b[3]=wmma::__float_to_tf32(rb0.w);
        b[4]=wmma::__float_to_tf32(rb1.x); b[5]=wmma::__float_to_tf32(rb1.y);
        b[6]=wmma::__float_to_tf32(rb1.z); b[7]=wmma::__float_to_tf32(rb1.w);
    };

    ldA(0); ldB(0); stStage(0); __syncthreads();
    const int NIT = 1024 / 16;
    for (int it = 0; it < NIT; it++) {
        int buf = it & 1;
        if (it < NIT - 1) { ldA((it + 1) * 16); ldB((it + 1) * 16); }
#pragma unroll
        for (int ks = 0; ks < 2; ks++) {
            wmma::fragment<wmma::matrix_a, 16, 16, 8, wmma::precision::tf32, wmma::row_major> af[2];
            wmma::fragment<wmma::matrix_b, 16, 16, 8, wmma::precision::tf32, wmma::row_major> bf[2];
#pragma unroll
            for (int i = 0; i < 2; i++)
                wmma::load_matrix_sync(af[i], As + buf*64*20 + (wm*32 + i*16)*20 + ks*8, 20);
#pragma unroll
            for (int j = 0; j < 2; j++)
                wmma::load_matrix_sync(bf[j], Bs + buf*16*136 + ks*8*136 + wn*32 + j*16, 136);
#pragma unroll
            for (int i = 0; i < 2; i++)
#pragma unroll
                for (int j = 0; j < 2; j++) wmma::mma_sync(acc[i][j], af[i], bf[j], acc[i][j]);
        }
        if (it < NIT - 1) stStage(buf ^ 1);
        __syncthreads();
    }
#pragma unroll
    for (int i = 0; i < 2; i++)
#pragma unroll
        for (int j = 0; j < 2; j++)
            wmma::store_matrix_sync(Cs + (wm*32 + i*16)*132 + wn*32 + j*16,
                                    acc[i][j], 132, wmma::mem_row_major);
    __syncthreads();
    {
        int b = tid >> 2, seg = tid & 3;
#pragma unroll
        for (int k = 0; k < 32; k++)
            outp[(size_t)b * G4 + n0 + seg * 32 + k] = Cs[b * 132 + seg * 32 + k];
    }
}

// ---------------- 7: LSTM elementwise ----------------
__global__ void k_lstm(const float* __restrict__ c_prev,
                       const float* __restrict__ b_lstm,
                       float* __restrict__ out_ht,
                       float* __restrict__ out_ct) {
    int idx = blockIdx.x * 256 + threadIdx.x;
    int b = idx >> 11, n = idx & 2047;
    const float* g0 = g_gp[0] + (size_t)b * G4;
    const float* g1 = g_gp[1] + (size_t)b * G4;
    const float* g2 = g_gp[2] + (size_t)b * G4;
    float i_ = g0[n]        + g1[n]        + g2[n]        + b_lstm[n];
    float f_ = g0[n + 2048] + g1[n + 2048] + g2[n + 2048] + b_lstm[n + 2048];
    float gg = g0[n + 4096] + g1[n + 4096] + g2[n + 4096] + b_lstm[n + 4096];
    float o_ = g0[n + 6144] + g1[n + 6144] + g2[n + 6144] + b_lstm[n + 6144];
    float c = sigmoid_acc(f_) * c_prev[idx] + sigmoid_acc(i_) * tanhf(gg);
    out_ct[idx] = c;
    float h = sigmoid_acc(o_) * tanhf(c);
    if (n < 1024) out_ht[b * 1024 + n] = h;
}

// ============================================================
// 8: decoded = ht @ dec_w^T + dec_b — tf32 wmma
// ============================================================
__global__ __launch_bounds__(256) void k_dec(const float* __restrict__ dec_w,
                                             const float* __restrict__ dec_b,
                                             const float* __restrict__ ht,
                                             float* __restrict__ out) {
    __shared__ float sm[8448];
    float* As  = sm;
    float* Bs  = sm + 2 * 128 * 20;
    float* CsT = sm;

    const int v0  = blockIdx.x * 128;
    const int tid = threadIdx.x;
    const int wid = tid >> 5;
    const int wm  = wid >> 1, wn = wid & 1;

    wmma::fragment<wmma::accumulator, 16, 16, 8, float> acc[2][2];
#pragma unroll
    for (int i = 0; i < 2; i++)
#pragma unroll
        for (int j = 0; j < 2; j++) wmma::fill_fragment(acc[i][j], 0.0f);

    const int ar = tid >> 1, ah = tid & 1;
    const int bb = tid >> 2, bq = tid & 3;

    float4 ra0, ra1, rb;
    auto ldA = [&](int k0) {
        if (v0 + ar < NVOC) {
            const float* p = dec_w + (size_t)(v0 + ar) * 1024 + k0 + ah * 8;
            ra0 = *(const float4*)p; ra1 = *(const float4*)(p + 4);
        } else {
            ra0 = make_float4(0,0,0,0); ra1 = ra0;
        }
    };
    auto ldB = [&](int k0) { rb = *(const float4*)(ht + bb * 1024 + k0 + bq * 4); };
    auto stStage = [&](int buf) {
        float* a = As + buf * 128 * 20 + ar * 20 + ah * 8;
        a[0]=wmma::__float_to_tf32(ra0.x); a[1]=wmma::__float_to_tf32(ra0.y);
        a[2]=wmma::__float_to_tf32(ra0.z); a[3]=wmma::__float_to_tf32(ra0.w);
        a[4]=wmma::__float_to_tf32(ra1.x); a[5]=wmma::__float_to_tf32(ra1.y);
        a[6]=wmma::__float_to_tf32(ra1.z); a[7]=wmma::__float_to_tf32(ra1.w);
        float* b = Bs + buf * 64 * 20 + bb * 20 + bq * 4;
        b[0]=wmma::__float_to_tf32(rb.x); b[1]=wmma::__float_to_tf32(rb.y);
        b[2]=wmma::__float_to_tf32(rb.z); b[3]=wmma::__float_to_tf32(rb.w);
    };

    ldA(0); ldB(0); stStage(0); __syncthreads();
    for (int it = 0; it < 64; it++) {
        int buf = it & 1;
        if (it < 63) { ldA((it + 1) * 16); ldB((it + 1) * 16); }
#pragma unroll
        for (int ks = 0; ks < 2; ks++) {
            wmma::fragment<wmma::matrix_a, 16, 16, 8, wmma::precision::tf32, wmma::row_major> af[2];
            wmma::fragment<wmma::matrix_b, 16, 16, 8, wmma::precision::tf32, wmma::col_major> bf[2];
#pragma unroll
            for (int i = 0; i < 2; i++)
                wmma::load_matrix_sync(af[i], As + buf*128*20 + (wm*32 + i*16)*20 + ks*8, 20);
#pragma unroll
            for (int j = 0; j < 2; j++)
                wmma::load_matrix_sync(bf[j], Bs + buf*64*20 + (wn*32 + j*16)*20 + ks*8, 20);
#pragma unroll
            for (int i = 0; i < 2; i++)
#pragma unroll
                for (int j = 0; j < 2; j++) wmma::mma_sync(acc[i][j], af[i], bf[j], acc[i][j]);
        }
        if (it < 63) stStage(buf ^ 1);
        __syncthreads();
    }
#pragma unroll
    for (int i = 0; i < 2; i++)
#pragma unroll
        for (int j = 0; j < 2; j++)
            wmma::store_matrix_sync(CsT + (wn*32 + j*16)*132 + wm*32 + i*16,
                                    acc[i][j], 132, wmma::mem_col_major);
    __syncthreads();
    {
        int b = tid >> 2, seg = tid & 3;
#pragma unroll
        for (int k = 0; k < 32; k++) {
            int v = v0 + seg * 32 + k;
            if (v < NVOC)
                out[(size_t)b * NVOC + v] = CsT[b * 132 + seg * 32 + k] + __ldg(dec_b + v);
        }
    }
}

// ---------------- launch ----------------
extern "C" void kernel_launch(void* const* d_in, const int* in_sizes, int n_in,
                              void* d_out, int out_size) {
    const int*   inputs   = (const int*)  d_in[0];
    const float* mem      = (const float*)d_in[1];
    const float* h_prev   = (const float*)d_in[2];
    const float* c_prev   = (const float*)d_in[3];
    const float* enc_w    = (const float*)d_in[4];
    const float* attWa    = (const float*)d_in[5];
    const float* attUa    = (const float*)d_in[6];
    const float* attV     = (const float*)d_in[7];
    const float* W_ih     = (const float*)d_in[8];
    const float* W_hh     = (const float*)d_in[9];
    const float* b_lstm   = (const float*)d_in[10];
    const float* dec_w    = (const float*)d_in[11];
    const float* dec_b    = (const float*)d_in[12];

    float* out      = (float*)d_out;
    float* out_dec  = out;
    float* out_ht   = out + (size_t)BB * NVOC;
    float* out_ct   = out_ht + (size_t)BB * NH;

    // unconditional + idempotent: identical work on every call (no static guard)
    cudaFuncSetAttribute(k_att, cudaFuncAttributeMaxDynamicSharedMemorySize, AT_SMEM);

    k_pre<<<1280, 256>>>(inputs, enc_w, attUa);
    k_wa<<<8, 256>>>(h_prev, attWa);
    k_att<<<1024, 256, AT_SMEM>>>(mem, attV);
    k_softmax<<<64, 256>>>();
    k_ctx<<<dim3(4, 64), 256>>>(mem);
    k_gates<<<dim3(64, 3), 256>>>(h_prev, W_ih, W_hh);
    k_lstm<<<(BB * H2) / 256, 256>>>(c_prev, b_lstm, out_ht, out_ct);
    k_dec<<<(NVOC + 127) / 128, 256>>>(dec_w, dec_b, out_ht, out_dec);
}